// round 13
// baseline (speedup 1.0000x reference)
#include <cuda_runtime.h>
#include <cuda_fp16.h>
#include <math.h>
#include <stdint.h>

#define Bsz   4096
#define Nn    32
#define Hh    8
#define Dd    64
#define HIDd  512
#define MROWS (Bsz * Nn)
#define QKV_COLS (3 * HIDd)
#define Kdim  512

static const size_t OUT_ELEMS  = (size_t)MROWS * HIDd;
static const size_t ATTN_ELEMS = (size_t)Bsz * Hh * Nn * Nn;

__device__ float g_outfb[(size_t)MROWS * HIDd];     // fallback out scratch
__device__ __half g_Ahi[(size_t)MROWS * HIDd];      // X fp16, then ctx fp16
__device__ __half g_Whi[1048576 + 16];
__device__ float g_attn_fb[(size_t)Bsz * Hh * Nn * Nn];
__device__ unsigned int g_mask_bits[32];

#define WQKV_ELE (QKV_COLS * HIDd)

// ---------------- PTX helpers ----------------
__device__ __forceinline__ uint32_t smem_u32(const void* p) {
    uint32_t a;
    asm("{ .reg .u64 t; cvta.to.shared.u64 t, %1; cvt.u32.u64 %0, t; }"
        : "=r"(a) : "l"(p));
    return a;
}
__device__ __forceinline__ void cp16(uint32_t dst, const void* src) {
    asm volatile("cp.async.cg.shared.global [%0], [%1], 16;"
                 :: "r"(dst), "l"(src) : "memory");
}
#define CP_COMMIT() asm volatile("cp.async.commit_group;" ::: "memory")
#define CP_WAIT2()  asm volatile("cp.async.wait_group 2;" ::: "memory")
#define CP_WAIT1()  asm volatile("cp.async.wait_group 1;" ::: "memory")
#define CP_WAIT0()  asm volatile("cp.async.wait_group 0;" ::: "memory")

#define LDSM4(r0, r1, r2, r3, addr) \
    asm volatile("ldmatrix.sync.aligned.m8n8.x4.shared.b16 {%0,%1,%2,%3}, [%4];" \
        : "=r"(r0), "=r"(r1), "=r"(r2), "=r"(r3) : "r"(addr))

#define MMA16816(c, a, b0, b1) \
    asm volatile("mma.sync.aligned.m16n8k16.row.col.f32.f16.f16.f32 " \
        "{%0,%1,%2,%3}, {%4,%5,%6,%7}, {%8,%9}, {%0,%1,%2,%3};" \
        : "+f"((c)[0]), "+f"((c)[1]), "+f"((c)[2]), "+f"((c)[3]) \
        : "r"((a)[0]), "r"((a)[1]), "r"((a)[2]), "r"((a)[3]), \
          "r"(b0), "r"(b1))

// ---------------- mask decode ----------------
__global__ void decode_mask_kernel(const unsigned char* __restrict__ raw) {
    __shared__ int onebyte;
    if (threadIdx.x == 0) {
        int ok = 1;
        for (int i = 0; i < 32; ++i) if (raw[33 * i] == 0) ok = 0;
        onebyte = ok;
    }
    __syncthreads();
    int i = threadIdx.x;
    unsigned int bits = 0;
    if (onebyte) {
        for (int j = 0; j < 32; ++j)
            if (raw[i * 32 + j] != 0) bits |= (1u << j);
    } else {
        const unsigned int* w = (const unsigned int*)raw;
        for (int j = 0; j < 32; ++j)
            if (w[i * 32 + j] != 0) bits |= (1u << j);
    }
    g_mask_bits[i] = bits;
}

// ---------------- fp32 -> fp16 convert ----------------
__global__ void __launch_bounds__(256)
split_hi_kernel(const float* __restrict__ in, __half* __restrict__ hi, int n4)
{
    int i = blockIdx.x * 256 + threadIdx.x;
    if (i >= n4) return;
    float4 x = ((const float4*)in)[i];
    __half2 h0; h0.x = __float2half_rn(x.x); h0.y = __float2half_rn(x.y);
    __half2 h1; h1.x = __float2half_rn(x.z); h1.y = __float2half_rn(x.w);
    ((__half2*)hi)[2 * i + 0] = h0;
    ((__half2*)hi)[2 * i + 1] = h1;
}

// ============================================================================
// Fused QKV-GEMM + attention.
// CTA tile: M=64 (2 batches x 32 tokens) x N=192 (q|k|v strips of head h),
// K=512. 8 warps, warp tile 32x48, KC=32, 3-stage cp.async.
// Epilogue: acc+bias -> smem Q/K/V (reusing stage smem), then 2x128-thread
// attention; writes attn (fp32) + ctx (fp16) to DRAM. qkv never hits DRAM.
// ============================================================================
#define FGM 64
#define FGN 192
#define FKC 32
#define FNCHUNK (Kdim / FKC)          // 16
#define FPITCH 80
#define FA_BYTES (64 * FPITCH)        // 5120
#define FB_BYTES (192 * FPITCH)       // 15360
#define FSTAGE (FA_BYTES + FB_BYTES)  // 20480
#define FSMEM (3 * FSTAGE + 192 * 4)  // 62208
// attention smem (overlaps the 3 stages, 59392 <= 61440):
#define OFF_QS 0
#define OFF_KS 16384
#define OFF_VS 33792
#define OFF_PS 50176

__global__ void __launch_bounds__(256, 2)
fused_qkv_attn(const __half* __restrict__ Ahi, const __half* __restrict__ Whi,
               const float* __restrict__ bqkv, __half* __restrict__ chi,
               float* __restrict__ attn_out)
{
    extern __shared__ char smem[];
    const uint32_t sb = smem_u32(smem);
    const int t = threadIdx.x, wid = t >> 5, lane = t & 31;
    const int h  = blockIdx.x;             // head
    const int bm = blockIdx.y * FGM;       // global row base (2 batches)
    const int wm = (wid & 1) * 32;         // warp M offset
    const int wn = (wid >> 1) * 48;        // warp N offset

    float* bias_s = (float*)(smem + 3 * FSTAGE);
    if (t < 192) {
        int tt = t >> 6, d = t & 63;
        bias_s[t] = bqkv[tt * 512 + h * 64 + d];
    }

    float acc[2][6][4];
#pragma unroll
    for (int i = 0; i < 2; ++i)
#pragma unroll
        for (int j = 0; j < 6; ++j)
#pragma unroll
            for (int q = 0; q < 4; ++q) acc[i][j][q] = 0.0f;

    auto load_stage = [&](int st, int k0) {
        uint32_t base = sb + st * (uint32_t)FSTAGE;
#pragma unroll
        for (int it = 0; it < 4; ++it) {
            int idx = t + 256 * it;        // 0..1023
            int r = idx >> 2, seg = idx & 3;
            if (r < 64) {
                uint32_t doff = (uint32_t)(r * FPITCH + seg * 16);
                size_t so = (size_t)(bm + r) * Kdim + k0 + seg * 8;
                cp16(base + doff, Ahi + so);
            } else {
                int rb = r - 64;           // 0..191
                int tt = rb >> 6, d = rb & 63;
                uint32_t doff = (uint32_t)(rb * FPITCH + seg * 16);
                size_t so = (size_t)(tt * 512 + h * 64 + d) * Kdim + k0 + seg * 8;
                cp16(base + FA_BYTES + doff, Whi + so);
            }
        }
        CP_COMMIT();
    };

    load_stage(0, 0);
    load_stage(1, FKC);

    const uint32_t lrow  = lane & 15;
    const uint32_t lcolb = (lane >> 4) * 16;

    for (int c = 0; c < FNCHUNK; ++c) {
        if (c + 2 < FNCHUNK) {
            load_stage((c + 2) % 3, (c + 2) * FKC);
            CP_WAIT2();
        } else if (c + 1 < FNCHUNK) {
            CP_WAIT1();
        } else {
            CP_WAIT0();
        }
        __syncthreads();

        uint32_t base = sb + (uint32_t)(c % 3) * FSTAGE;
#pragma unroll
        for (int s = 0; s < 2; ++s) {
            uint32_t colb = s * 32 + lcolb;
            uint32_t Ah[2][4];
#pragma unroll
            for (int mi = 0; mi < 2; ++mi) {
                uint32_t ad = base + (wm + mi * 16 + lrow) * FPITCH + colb;
                LDSM4(Ah[mi][0], Ah[mi][1], Ah[mi][2], Ah[mi][3], ad);
            }
#pragma unroll
            for (int ni = 0; ni < 3; ++ni) {
                uint32_t bd = base + FA_BYTES
                            + (wn + ni * 16 + lrow) * FPITCH + colb;
                uint32_t h0, h1, h2, h3;
                LDSM4(h0, h1, h2, h3, bd);
#pragma unroll
                for (int mi = 0; mi < 2; ++mi) {
                    MMA16816(acc[mi][2 * ni],     Ah[mi], h0, h2);
                    MMA16816(acc[mi][2 * ni + 1], Ah[mi], h1, h3);
                }
            }
        }
        __syncthreads();
    }

    // ---- epilogue: acc + bias -> smem Q/K/V (stage smem now dead) ----
    float (*Qs)[32][64] = (float(*)[32][64])(smem + OFF_QS);
    float (*Ks)[32][68] = (float(*)[32][68])(smem + OFF_KS);
    float (*Vs)[32][64] = (float(*)[32][64])(smem + OFF_VS);
    float (*Ps)[32][36] = (float(*)[32][36])(smem + OFF_PS);

    {
        const int row0 = wm + (lane >> 2);
        const int col0 = wn + (lane & 3) * 2;
#pragma unroll
        for (int mi = 0; mi < 2; ++mi)
#pragma unroll
            for (int nj = 0; nj < 6; ++nj)
#pragma unroll
                for (int q = 0; q < 4; ++q) {
                    int r  = row0 + mi * 16 + ((q >> 1) << 3);
                    int cc = col0 + nj * 8 + (q & 1);
                    float val = acc[mi][nj][q] + bias_s[cc];
                    int tt = cc >> 6, d = cc & 63;
                    int bl = r >> 5, i = r & 31;
                    if (tt == 0)      Qs[bl][i][d] = val;
                    else if (tt == 1) Ks[bl][i][d] = val;
                    else              Vs[bl][i][d] = val;
                }
    }
    __syncthreads();

    // ---- attention: warpgroup wg handles batch (blockIdx.y*2 + wg) ----
    const int wg   = t >> 7;         // 0/1
    const int wt   = t & 127;
    const int awid = wt >> 5;        // 0..3
    const int b    = blockIdx.y * 2 + wg;
    const int bh   = b * 8 + h;

    {   // scores + softmax: warp awid owns rows [8a,8a+8), lane = column j
        const int j = lane;
        float a8[8];
#pragma unroll
        for (int r = 0; r < 8; ++r) a8[r] = 0.0f;
#pragma unroll 4
        for (int d4 = 0; d4 < 16; ++d4) {
            float4 kv = *(const float4*)&Ks[wg][j][4 * d4];
#pragma unroll
            for (int r = 0; r < 8; ++r) {
                float4 qv = *(const float4*)&Qs[wg][awid * 8 + r][4 * d4];
                a8[r] += qv.x * kv.x + qv.y * kv.y + qv.z * kv.z + qv.w * kv.w;
            }
        }
        size_t abase = (size_t)bh * 1024;
#pragma unroll
        for (int r = 0; r < 8; ++r) {
            int i = awid * 8 + r;
            float s = ((g_mask_bits[i] >> j) & 1u) ? a8[r] * 0.125f : -1e9f;
            float mx = s;
#pragma unroll
            for (int o = 16; o; o >>= 1)
                mx = fmaxf(mx, __shfl_xor_sync(0xFFFFFFFFu, mx, o));
            float e = expf(s - mx);
            float sum = e;
#pragma unroll
            for (int o = 16; o; o >>= 1)
                sum += __shfl_xor_sync(0xFFFFFFFFu, sum, o);
            float pr = e / sum;
            Ps[wg][i][j] = pr;
            attn_out[abase + (size_t)i * 32 + j] = pr;
        }
    }
    __syncthreads();

    {   // PV + fp16 ctx store
        const int d  = wt & 63;
        const int hh = wt >> 6;
        float a2[16];
#pragma unroll
        for (int r = 0; r < 16; ++r) a2[r] = 0.0f;
#pragma unroll 2
        for (int j4 = 0; j4 < 8; ++j4) {
            float v0 = Vs[wg][4 * j4 + 0][d];
            float v1 = Vs[wg][4 * j4 + 1][d];
            float v2 = Vs[wg][4 * j4 + 2][d];
            float v3 = Vs[wg][4 * j4 + 3][d];
#pragma unroll
            for (int r = 0; r < 16; ++r) {
                float4 p = *(const float4*)&Ps[wg][hh * 16 + r][4 * j4];
                a2[r] += p.x * v0 + p.y * v1 + p.z * v2 + p.w * v3;
            }
        }
        size_t cb = (size_t)b * Nn * HIDd + h * Dd + d;
#pragma unroll
        for (int r = 0; r < 16; ++r)
            chi[cb + (size_t)(hh * 16 + r) * HIDd] = __float2half_rn(a2[r]);
    }
}

// ---------------- mma.sync fp16 GEMM (NT), R12 config (GEMM2) --------------
#define GM  128
#define GN  128
#define GKC 32
#define NCHUNK (Kdim / GKC)       // 16
#define APITCH 80
#define MAT_BYTES (128 * APITCH)  // 10240
#define STAGE_BYTES (2 * MAT_BYTES)   // 20480
#define GEMM_SMEM (3 * STAGE_BYTES)   // 61440

__global__ void __launch_bounds__(256, 2)
gemm_tc(const __half* __restrict__ Ahi, const __half* __restrict__ Bhi,
        const float* __restrict__ bias, float* __restrict__ C, int Nc)
{
    extern __shared__ char smem[];
    const uint32_t sb = smem_u32(smem);
    const int t = threadIdx.x, wid = t >> 5, lane = t & 31;
    const int bm = blockIdx.y * GM, bn = blockIdx.x * GN;
    const int wm = (wid & 3) * 32;
    const int wn = (wid >> 2) * 64;

    float acc[2][8][4];
#pragma unroll
    for (int i = 0; i < 2; ++i)
#pragma unroll
        for (int j = 0; j < 8; ++j)
#pragma unroll
            for (int q = 0; q < 4; ++q) acc[i][j][q] = 0.0f;

    auto load_stage = [&](int st, int k0) {
        uint32_t base = sb + st * (uint32_t)STAGE_BYTES;
#pragma unroll
        for (int it = 0; it < 2; ++it) {
            int idx = t + 256 * it;
            int r = idx >> 2, seg = idx & 3;
            uint32_t doff = (uint32_t)(r * APITCH + seg * 16);
            size_t soA = (size_t)(bm + r) * Kdim + k0 + seg * 8;
            size_t soB = (size_t)(bn + r) * Kdim + k0 + seg * 8;
            cp16(base + doff,             Ahi + soA);
            cp16(base + MAT_BYTES + doff, Bhi + soB);
        }
        CP_COMMIT();
    };

    load_stage(0, 0);
    load_stage(1, GKC);

    const uint32_t lrow  = lane & 15;
    const uint32_t lcolb = (lane >> 4) * 16;

    for (int c = 0; c < NCHUNK; ++c) {
        if (c + 2 < NCHUNK) {
            load_stage((c + 2) % 3, (c + 2) * GKC);
            CP_WAIT2();
        } else if (c + 1 < NCHUNK) {
            CP_WAIT1();
        } else {
            CP_WAIT0();
        }
        __syncthreads();

        uint32_t base = sb + (uint32_t)(c % 3) * STAGE_BYTES;
#pragma unroll
        for (int s = 0; s < 2; ++s) {
            uint32_t colb = s * 32 + lcolb;
            uint32_t Ah[2][4];
#pragma unroll
            for (int mi = 0; mi < 2; ++mi) {
                uint32_t ad = base + (wm + mi * 16 + lrow) * APITCH + colb;
                LDSM4(Ah[mi][0], Ah[mi][1], Ah[mi][2], Ah[mi][3], ad);
            }
#pragma unroll
            for (int ni = 0; ni < 4; ++ni) {
                uint32_t bd = base + MAT_BYTES
                            + (wn + ni * 16 + lrow) * APITCH + colb;
                uint32_t h0, h1, h2, h3;
                LDSM4(h0, h1, h2, h3, bd);
#pragma unroll
                for (int mi = 0; mi < 2; ++mi) {
                    MMA16816(acc[mi][2 * ni],     Ah[mi], h0, h2);
                    MMA16816(acc[mi][2 * ni + 1], Ah[mi], h1, h3);
                }
            }
        }
        __syncthreads();
    }

    const int row0 = bm + wm + (lane >> 2);
    const int col0 = bn + wn + (lane & 3) * 2;
#pragma unroll
    for (int mi = 0; mi < 2; ++mi) {
#pragma unroll
        for (int nj = 0; nj < 8; ++nj) {
            int r = row0 + mi * 16;
            int cc = col0 + nj * 8;
            float b0 = __ldg(&bias[cc]), b1 = __ldg(&bias[cc + 1]);
            float* p0 = C + (size_t)r * Nc + cc;
            float* p1 = C + (size_t)(r + 8) * Nc + cc;
            p0[0] = acc[mi][nj][0] + b0;
            p0[1] = acc[mi][nj][1] + b1;
            p1[0] = acc[mi][nj][2] + b0;
            p1[1] = acc[mi][nj][3] + b1;
        }
    }
}

// ---------------- launch ----------------
extern "C" void kernel_launch(void* const* d_in, const int* in_sizes, int n_in,
                              void* d_out, int out_size) {
    const float*         X    = (const float*)d_in[0];
    const unsigned char* mask = (const unsigned char*)d_in[1];
    const float*         Wqkv = (const float*)d_in[2];
    const float*         bqkv = (const float*)d_in[3];
    const float*         Wo   = (const float*)d_in[4];
    const float*         bo   = (const float*)d_in[5];

    float *outfb_p, *attn_fb_p;
    __half *ahi_p, *whi_p;
    cudaGetSymbolAddress((void**)&outfb_p, g_outfb);
    cudaGetSymbolAddress((void**)&attn_fb_p, g_attn_fb);
    cudaGetSymbolAddress((void**)&ahi_p, g_Ahi);
    cudaGetSymbolAddress((void**)&whi_p, g_Whi);

    float* out = (float*)d_out;
    float *out_p, *attn_p;
    long long osz = (long long)out_size;
    if (osz >= (long long)(OUT_ELEMS + ATTN_ELEMS)) {
        out_p = out; attn_p = out + OUT_ELEMS;
    } else if (osz >= (long long)OUT_ELEMS) {
        out_p = out; attn_p = attn_fb_p;
    } else {
        attn_p = out; out_p = outfb_p;
    }

    cudaFuncSetAttribute(gemm_tc, cudaFuncAttributeMaxDynamicSharedMemorySize,
                         GEMM_SMEM);
    cudaFuncSetAttribute(fused_qkv_attn,
                         cudaFuncAttributeMaxDynamicSharedMemorySize, FSMEM);

    decode_mask_kernel<<<1, 32>>>(mask);

    // converts: X, Wqkv, Wo -> fp16
    {
        int n4 = (MROWS * HIDd) / 4;
        split_hi_kernel<<<(n4 + 255) / 256, 256>>>(X, ahi_p, n4);
        int w4 = WQKV_ELE / 4;
        split_hi_kernel<<<(w4 + 255) / 256, 256>>>(Wqkv, whi_p, w4);
        int o4 = (HIDd * HIDd) / 4;
        split_hi_kernel<<<(o4 + 255) / 256, 256>>>(Wo, whi_p + WQKV_ELE, o4);
    }

    // fused qkv-GEMM + attention: writes attn + ctx(fp16, into g_Ahi)
    // NOTE: g_Ahi holds X(fp16) as GEMM input and receives ctx(fp16).
    // Each CTA reads A rows [bm, bm+64) and writes ctx to the SAME rows —
    // but only after consuming all of A for those rows (K loop done), and
    // no other CTA reads those rows (row blocks are disjoint across CTAs
    // except the 8 head-CTAs sharing them). Head CTAs sharing rows run
    // concurrently, so in-place is UNSAFE across heads -> write ctx to a
    // separate buffer region instead: reuse g_Whi tail? Too small. Use
    // dedicated ctx buffer below.
    {
        static __half* ctx_p = nullptr;  // resolved once per process
        // ctx buffer: reuse g_outfb (float scratch, 268MB) as __half storage
        ctx_p = (__half*)outfb_p;
        if (out_p == outfb_p) {
            // fallback path also needs outfb for final out; ctx fits in the
            // second half (ctx needs 134MB of the 268MB buffer)
            ctx_p = (__half*)(outfb_p);  // out written after ctx consumed? No:
            // GEMM2 reads ctx and writes out_p. If both alias outfb, GEMM2
            // would overwrite its own input. Shift ctx to upper half:
            ctx_p = (__half*)(outfb_p + OUT_ELEMS / 2);
        }
        fused_qkv_attn<<<dim3(Hh, MROWS / FGM), 256, FSMEM>>>(
            ahi_p, whi_p, bqkv, ctx_p, attn_p);

        // out = ctx @ Wo^T + bo     [131072 x 512]
        gemm_tc<<<dim3(HIDd / GN, MROWS / GM), 256, GEMM_SMEM>>>(
            ctx_p, whi_p + WQKV_ELE, bo, out_p, HIDd);
    }
}

// round 14
// speedup vs baseline: 1.0985x; 1.0985x over previous
#include <cuda_runtime.h>
#include <cuda_fp16.h>
#include <math.h>
#include <stdint.h>

#define Bsz   4096
#define Nn    32
#define Hh    8
#define Dd    64
#define HIDd  512
#define MROWS (Bsz * Nn)
#define QKV_COLS (3 * HIDd)
#define Kdim  512

static const size_t OUT_ELEMS  = (size_t)MROWS * HIDd;
static const size_t ATTN_ELEMS = (size_t)Bsz * Hh * Nn * Nn;

__device__ __half g_qkvh[(size_t)MROWS * QKV_COLS];   // fp16 qkv (402MB)
__device__ __half g_Ahi[(size_t)MROWS * HIDd];        // X fp16, then ctx fp16
__device__ __half g_Whi[1048576 + 16];
__device__ float g_outfb[(size_t)MROWS * HIDd];       // fallback out scratch
__device__ float g_attn_fb[(size_t)Bsz * Hh * Nn * Nn];
__device__ unsigned int g_mask_bits[32];

#define WQKV_ELE (QKV_COLS * HIDd)

// ---------------- PTX helpers ----------------
__device__ __forceinline__ uint32_t smem_u32(const void* p) {
    uint32_t a;
    asm("{ .reg .u64 t; cvta.to.shared.u64 t, %1; cvt.u32.u64 %0, t; }"
        : "=r"(a) : "l"(p));
    return a;
}
__device__ __forceinline__ void cp16(uint32_t dst, const void* src) {
    asm volatile("cp.async.cg.shared.global [%0], [%1], 16;"
                 :: "r"(dst), "l"(src) : "memory");
}
#define CP_COMMIT() asm volatile("cp.async.commit_group;" ::: "memory")
#define CP_WAIT2()  asm volatile("cp.async.wait_group 2;" ::: "memory")
#define CP_WAIT1()  asm volatile("cp.async.wait_group 1;" ::: "memory")
#define CP_WAIT0()  asm volatile("cp.async.wait_group 0;" ::: "memory")

#define LDSM4(r0, r1, r2, r3, addr) \
    asm volatile("ldmatrix.sync.aligned.m8n8.x4.shared.b16 {%0,%1,%2,%3}, [%4];" \
        : "=r"(r0), "=r"(r1), "=r"(r2), "=r"(r3) : "r"(addr))

#define MMA16816(c, a, b0, b1) \
    asm volatile("mma.sync.aligned.m16n8k16.row.col.f32.f16.f16.f32 " \
        "{%0,%1,%2,%3}, {%4,%5,%6,%7}, {%8,%9}, {%0,%1,%2,%3};" \
        : "+f"((c)[0]), "+f"((c)[1]), "+f"((c)[2]), "+f"((c)[3]) \
        : "r"((a)[0]), "r"((a)[1]), "r"((a)[2]), "r"((a)[3]), \
          "r"(b0), "r"(b1))

// ---------------- mask decode ----------------
__global__ void decode_mask_kernel(const unsigned char* __restrict__ raw) {
    __shared__ int onebyte;
    if (threadIdx.x == 0) {
        int ok = 1;
        for (int i = 0; i < 32; ++i) if (raw[33 * i] == 0) ok = 0;
        onebyte = ok;
    }
    __syncthreads();
    int i = threadIdx.x;
    unsigned int bits = 0;
    if (onebyte) {
        for (int j = 0; j < 32; ++j)
            if (raw[i * 32 + j] != 0) bits |= (1u << j);
    } else {
        const unsigned int* w = (const unsigned int*)raw;
        for (int j = 0; j < 32; ++j)
            if (w[i * 32 + j] != 0) bits |= (1u << j);
    }
    g_mask_bits[i] = bits;
}

// ---------------- fp32 -> fp16 convert ----------------
__global__ void __launch_bounds__(256)
split_hi_kernel(const float* __restrict__ in, __half* __restrict__ hi, int n4)
{
    int i = blockIdx.x * 256 + threadIdx.x;
    if (i >= n4) return;
    float4 x = ((const float4*)in)[i];
    __half2 h0; h0.x = __float2half_rn(x.x); h0.y = __float2half_rn(x.y);
    __half2 h1; h1.x = __float2half_rn(x.z); h1.y = __float2half_rn(x.w);
    ((__half2*)hi)[2 * i + 0] = h0;
    ((__half2*)hi)[2 * i + 1] = h1;
}

// ---------------- mma.sync fp16 GEMM (NT), R12 config -----------------------
// C[m,n] = sum_k A[m,k]*B[n,k] + bias[n].
// CTA 128x128, 8 warps (warp tile 32x64), KC=32, 3-stage cp.async.
// out_half: 1 -> store __half2 into Ch, 0 -> store fp32 into Cf.
#define GM  128
#define GN  128
#define GKC 32
#define NCHUNK (Kdim / GKC)       // 16
#define APITCH 80                 // 32 fp16 + 16B pad per smem row
#define MAT_BYTES (128 * APITCH)  // 10240
#define STAGE_BYTES (2 * MAT_BYTES)   // 20480
#define GEMM_SMEM (3 * STAGE_BYTES)   // 61440

__global__ void __launch_bounds__(256, 2)
gemm_tc(const __half* __restrict__ Ahi, const __half* __restrict__ Bhi,
        const float* __restrict__ bias, float* __restrict__ Cf,
        __half* __restrict__ Ch, int Nc, int out_half)
{
    extern __shared__ char smem[];
    const uint32_t sb = smem_u32(smem);
    const int t = threadIdx.x, wid = t >> 5, lane = t & 31;
    const int bm = blockIdx.y * GM, bn = blockIdx.x * GN;
    const int wm = (wid & 3) * 32;
    const int wn = (wid >> 2) * 64;

    float acc[2][8][4];
#pragma unroll
    for (int i = 0; i < 2; ++i)
#pragma unroll
        for (int j = 0; j < 8; ++j)
#pragma unroll
            for (int q = 0; q < 4; ++q) acc[i][j][q] = 0.0f;

    auto load_stage = [&](int st, int k0) {
        uint32_t base = sb + st * (uint32_t)STAGE_BYTES;
#pragma unroll
        for (int it = 0; it < 2; ++it) {
            int idx = t + 256 * it;
            int r = idx >> 2, seg = idx & 3;
            uint32_t doff = (uint32_t)(r * APITCH + seg * 16);
            size_t soA = (size_t)(bm + r) * Kdim + k0 + seg * 8;
            size_t soB = (size_t)(bn + r) * Kdim + k0 + seg * 8;
            cp16(base + doff,             Ahi + soA);
            cp16(base + MAT_BYTES + doff, Bhi + soB);
        }
        CP_COMMIT();
    };

    load_stage(0, 0);
    load_stage(1, GKC);

    const uint32_t lrow  = lane & 15;
    const uint32_t lcolb = (lane >> 4) * 16;

    for (int c = 0; c < NCHUNK; ++c) {
        if (c + 2 < NCHUNK) {
            load_stage((c + 2) % 3, (c + 2) * GKC);
            CP_WAIT2();
        } else if (c + 1 < NCHUNK) {
            CP_WAIT1();
        } else {
            CP_WAIT0();
        }
        __syncthreads();

        uint32_t base = sb + (uint32_t)(c % 3) * STAGE_BYTES;
#pragma unroll
        for (int s = 0; s < 2; ++s) {
            uint32_t colb = s * 32 + lcolb;
            uint32_t Ah[2][4];
#pragma unroll
            for (int mi = 0; mi < 2; ++mi) {
                uint32_t ad = base + (wm + mi * 16 + lrow) * APITCH + colb;
                LDSM4(Ah[mi][0], Ah[mi][1], Ah[mi][2], Ah[mi][3], ad);
            }
#pragma unroll
            for (int ni = 0; ni < 4; ++ni) {
                uint32_t bd = base + MAT_BYTES
                            + (wn + ni * 16 + lrow) * APITCH + colb;
                uint32_t h0, h1, h2, h3;
                LDSM4(h0, h1, h2, h3, bd);
#pragma unroll
                for (int mi = 0; mi < 2; ++mi) {
                    MMA16816(acc[mi][2 * ni],     Ah[mi], h0, h2);
                    MMA16816(acc[mi][2 * ni + 1], Ah[mi], h1, h3);
                }
            }
        }
        __syncthreads();
    }

    const int row0 = bm + wm + (lane >> 2);
    const int col0 = bn + wn + (lane & 3) * 2;
    if (out_half) {
#pragma unroll
        for (int mi = 0; mi < 2; ++mi) {
#pragma unroll
            for (int nj = 0; nj < 8; ++nj) {
                int r = row0 + mi * 16;
                int cc = col0 + nj * 8;
                float b0 = __ldg(&bias[cc]), b1 = __ldg(&bias[cc + 1]);
                __half2 v0, v1;
                v0.x = __float2half_rn(acc[mi][nj][0] + b0);
                v0.y = __float2half_rn(acc[mi][nj][1] + b1);
                v1.x = __float2half_rn(acc[mi][nj][2] + b0);
                v1.y = __float2half_rn(acc[mi][nj][3] + b1);
                *(__half2*)&Ch[(size_t)r * Nc + cc]       = v0;
                *(__half2*)&Ch[(size_t)(r + 8) * Nc + cc] = v1;
            }
        }
    } else {
#pragma unroll
        for (int mi = 0; mi < 2; ++mi) {
#pragma unroll
            for (int nj = 0; nj < 8; ++nj) {
                int r = row0 + mi * 16;
                int cc = col0 + nj * 8;
                float b0 = __ldg(&bias[cc]), b1 = __ldg(&bias[cc + 1]);
                float* p0 = Cf + (size_t)r * Nc + cc;
                float* p1 = Cf + (size_t)(r + 8) * Nc + cc;
                p0[0] = acc[mi][nj][0] + b0;
                p0[1] = acc[mi][nj][1] + b1;
                p1[0] = acc[mi][nj][2] + b0;
                p1[1] = acc[mi][nj][3] + b1;
            }
        }
    }
}

// ---------------- attention (fp16 qkv in, float4 smem, ctx -> fp16) ---------
__global__ void __launch_bounds__(128)
attn_kernel2(const __half* __restrict__ qkv, __half* __restrict__ chi,
             float* __restrict__ attn_out)
{
    __shared__ float Qs[32][64];
    __shared__ float Ks[32][68];   // float4-aligned pitch
    __shared__ float Vs[32][64];
    __shared__ float Ps[32][36];

    const int bh = blockIdx.x;
    const int b  = bh >> 3;
    const int h  = bh & 7;
    const int t  = threadIdx.x;
    const int wid = t >> 5, lane = t & 31;

    const __half* base = qkv + (size_t)b * Nn * QKV_COLS + h * Dd;
#pragma unroll
    for (int r = 0; r < 2; ++r) {
        int idx = t + 128 * r;            // 0..255
        int i = idx >> 3, u = (idx & 7) * 8;
        size_t ro = (size_t)i * QKV_COLS + u;
        uint4 qu = *(const uint4*)&base[ro];
        uint4 ku = *(const uint4*)&base[ro + HIDd];
        uint4 vu = *(const uint4*)&base[ro + 2 * HIDd];
        const __half2* qh = (const __half2*)&qu;
        const __half2* kh = (const __half2*)&ku;
        const __half2* vh = (const __half2*)&vu;
#pragma unroll
        for (int p = 0; p < 4; ++p) {
            float2 qf = __half22float2(qh[p]);
            float2 kf = __half22float2(kh[p]);
            float2 vf = __half22float2(vh[p]);
            Qs[i][u + 2 * p]     = qf.x;
            Qs[i][u + 2 * p + 1] = qf.y;
            Ks[i][u + 2 * p]     = kf.x;
            Ks[i][u + 2 * p + 1] = kf.y;
            Vs[i][u + 2 * p]     = vf.x;
            Vs[i][u + 2 * p + 1] = vf.y;
        }
    }
    __syncthreads();

    {   // scores: warp wid owns rows [8w,8w+8), lane = column j. float4 dots.
        const int j = lane;
        float a8[8];
#pragma unroll
        for (int r = 0; r < 8; ++r) a8[r] = 0.0f;
#pragma unroll 4
        for (int d4 = 0; d4 < 16; ++d4) {
            float4 kv = *(const float4*)&Ks[j][4 * d4];
#pragma unroll
            for (int r = 0; r < 8; ++r) {
                float4 qv = *(const float4*)&Qs[wid * 8 + r][4 * d4];
                a8[r] += qv.x * kv.x + qv.y * kv.y + qv.z * kv.z + qv.w * kv.w;
            }
        }
        size_t abase = (size_t)bh * 1024;
#pragma unroll
        for (int r = 0; r < 8; ++r) {
            int i = wid * 8 + r;
            float s = ((g_mask_bits[i] >> j) & 1u) ? a8[r] * 0.125f : -1e9f;
            float mx = s;
#pragma unroll
            for (int o = 16; o; o >>= 1)
                mx = fmaxf(mx, __shfl_xor_sync(0xFFFFFFFFu, mx, o));
            float e = expf(s - mx);
            float sum = e;
#pragma unroll
            for (int o = 16; o; o >>= 1)
                sum += __shfl_xor_sync(0xFFFFFFFFu, sum, o);
            float pr = e / sum;
            Ps[i][j] = pr;
            attn_out[abase + (size_t)i * 32 + j] = pr;
        }
    }
    __syncthreads();

    {   // PV: thread -> (half hh, column d); float4 over j.
        const int d  = t & 63;
        const int hh = t >> 6;
        float a2[16];
#pragma unroll
        for (int r = 0; r < 16; ++r) a2[r] = 0.0f;
#pragma unroll 2
        for (int j4 = 0; j4 < 8; ++j4) {
            float v0 = Vs[4 * j4 + 0][d];
            float v1 = Vs[4 * j4 + 1][d];
            float v2 = Vs[4 * j4 + 2][d];
            float v3 = Vs[4 * j4 + 3][d];
#pragma unroll
            for (int r = 0; r < 16; ++r) {
                float4 p = *(const float4*)&Ps[hh * 16 + r][4 * j4];
                a2[r] += p.x * v0 + p.y * v1 + p.z * v2 + p.w * v3;
            }
        }
        size_t cb = (size_t)b * Nn * HIDd + h * Dd + d;
#pragma unroll
        for (int r = 0; r < 16; ++r)
            chi[cb + (size_t)(hh * 16 + r) * HIDd] = __float2half_rn(a2[r]);
    }
}

// ---------------- launch ----------------
extern "C" void kernel_launch(void* const* d_in, const int* in_sizes, int n_in,
                              void* d_out, int out_size) {
    const float*         X    = (const float*)d_in[0];
    const unsigned char* mask = (const unsigned char*)d_in[1];
    const float*         Wqkv = (const float*)d_in[2];
    const float*         bqkv = (const float*)d_in[3];
    const float*         Wo   = (const float*)d_in[4];
    const float*         bo   = (const float*)d_in[5];

    float *outfb_p, *attn_fb_p;
    __half *qkvh_p, *ahi_p, *whi_p;
    cudaGetSymbolAddress((void**)&outfb_p, g_outfb);
    cudaGetSymbolAddress((void**)&attn_fb_p, g_attn_fb);
    cudaGetSymbolAddress((void**)&qkvh_p, g_qkvh);
    cudaGetSymbolAddress((void**)&ahi_p, g_Ahi);
    cudaGetSymbolAddress((void**)&whi_p, g_Whi);

    float* out = (float*)d_out;
    float *out_p, *attn_p;
    long long osz = (long long)out_size;
    if (osz >= (long long)(OUT_ELEMS + ATTN_ELEMS)) {
        out_p = out; attn_p = out + OUT_ELEMS;
    } else if (osz >= (long long)OUT_ELEMS) {
        out_p = out; attn_p = attn_fb_p;
    } else {
        attn_p = out; out_p = outfb_p;
    }

    cudaFuncSetAttribute(gemm_tc, cudaFuncAttributeMaxDynamicSharedMemorySize,
                         GEMM_SMEM);

    decode_mask_kernel<<<1, 32>>>(mask);

    // converts: X, Wqkv, Wo -> fp16
    {
        int n4 = (MROWS * HIDd) / 4;
        split_hi_kernel<<<(n4 + 255) / 256, 256>>>(X, ahi_p, n4);
        int w4 = WQKV_ELE / 4;
        split_hi_kernel<<<(w4 + 255) / 256, 256>>>(Wqkv, whi_p, w4);
        int o4 = (HIDd * HIDd) / 4;
        split_hi_kernel<<<(o4 + 255) / 256, 256>>>(Wo, whi_p + WQKV_ELE, o4);
    }

    // qkv = X @ Wqkv^T + bqkv   [131072 x 1536], fp16 output
    gemm_tc<<<dim3(QKV_COLS / GN, MROWS / GM), 256, GEMM_SMEM>>>(
        ahi_p, whi_p, bqkv, nullptr, qkvh_p, QKV_COLS, 1);

    // attention: reads fp16 qkv, writes attn (fp32) + ctx (fp16 into g_Ahi)
    attn_kernel2<<<Bsz * Hh, 128>>>(qkvh_p, ahi_p, attn_p);

    // out = ctx @ Wo^T + bo     [131072 x 512], fp32 output
    gemm_tc<<<dim3(HIDd / GN, MROWS / GM), 256, GEMM_SMEM>>>(
        ahi_p, whi_p + WQKV_ELE, bo, out_p, nullptr, HIDd, 0);
}

// round 15
// speedup vs baseline: 1.3690x; 1.2462x over previous
#include <cuda_runtime.h>
#include <cuda_fp16.h>
#include <math.h>
#include <stdint.h>

#define Bsz   4096
#define Nn    32
#define Hh    8
#define Dd    64
#define HIDd  512
#define MROWS (Bsz * Nn)
#define QKV_COLS (3 * HIDd)
#define Kdim  512

static const size_t OUT_ELEMS  = (size_t)MROWS * HIDd;
static const size_t ATTN_ELEMS = (size_t)Bsz * Hh * Nn * Nn;

__device__ __half g_qkvh[(size_t)MROWS * QKV_COLS];   // fp16 qkv
__device__ __half g_Ahi[(size_t)MROWS * HIDd];        // X fp16, then ctx fp16
__device__ __half g_Whi[1048576 + 16];
__device__ float g_outfb[(size_t)MROWS * HIDd];
__device__ float g_attn_fb[(size_t)Bsz * Hh * Nn * Nn];
__device__ unsigned int g_mask_bits[32];

#define WQKV_ELE (QKV_COLS * HIDd)

// ---------------- PTX helpers ----------------
__device__ __forceinline__ uint32_t smem_u32(const void* p) {
    uint32_t a;
    asm("{ .reg .u64 t; cvta.to.shared.u64 t, %1; cvt.u32.u64 %0, t; }"
        : "=r"(a) : "l"(p));
    return a;
}
__device__ __forceinline__ void cp16(uint32_t dst, const void* src) {
    asm volatile("cp.async.cg.shared.global [%0], [%1], 16;"
                 :: "r"(dst), "l"(src) : "memory");
}
#define CP_COMMIT() asm volatile("cp.async.commit_group;" ::: "memory")
#define CP_WAIT2()  asm volatile("cp.async.wait_group 2;" ::: "memory")
#define CP_WAIT1()  asm volatile("cp.async.wait_group 1;" ::: "memory")
#define CP_WAIT0()  asm volatile("cp.async.wait_group 0;" ::: "memory")

#define LDSM4(r0, r1, r2, r3, addr) \
    asm volatile("ldmatrix.sync.aligned.m8n8.x4.shared.b16 {%0,%1,%2,%3}, [%4];" \
        : "=r"(r0), "=r"(r1), "=r"(r2), "=r"(r3) : "r"(addr))

#define LDSM4T(r0, r1, r2, r3, addr) \
    asm volatile("ldmatrix.sync.aligned.m8n8.x4.trans.shared.b16 {%0,%1,%2,%3}, [%4];" \
        : "=r"(r0), "=r"(r1), "=r"(r2), "=r"(r3) : "r"(addr))

#define MMA16816(c, a, b0, b1) \
    asm volatile("mma.sync.aligned.m16n8k16.row.col.f32.f16.f16.f32 " \
        "{%0,%1,%2,%3}, {%4,%5,%6,%7}, {%8,%9}, {%0,%1,%2,%3};" \
        : "+f"((c)[0]), "+f"((c)[1]), "+f"((c)[2]), "+f"((c)[3]) \
        : "r"((a)[0]), "r"((a)[1]), "r"((a)[2]), "r"((a)[3]), \
          "r"(b0), "r"(b1))

__device__ __forceinline__ uint32_t pkh2(float a, float b) {
    __half2 t = __floats2half2_rn(a, b);
    return *(uint32_t*)&t;
}

// ---------------- mask decode ----------------
__global__ void decode_mask_kernel(const unsigned char* __restrict__ raw) {
    __shared__ int onebyte;
    if (threadIdx.x == 0) {
        int ok = 1;
        for (int i = 0; i < 32; ++i) if (raw[33 * i] == 0) ok = 0;
        onebyte = ok;
    }
    __syncthreads();
    int i = threadIdx.x;
    unsigned int bits = 0;
    if (onebyte) {
        for (int j = 0; j < 32; ++j)
            if (raw[i * 32 + j] != 0) bits |= (1u << j);
    } else {
        const unsigned int* w = (const unsigned int*)raw;
        for (int j = 0; j < 32; ++j)
            if (w[i * 32 + j] != 0) bits |= (1u << j);
    }
    g_mask_bits[i] = bits;
}

// ---------------- fp32 -> fp16 convert ----------------
__global__ void __launch_bounds__(256)
split_hi_kernel(const float* __restrict__ in, __half* __restrict__ hi, int n4)
{
    int i = blockIdx.x * 256 + threadIdx.x;
    if (i >= n4) return;
    float4 x = ((const float4*)in)[i];
    __half2 h0; h0.x = __float2half_rn(x.x); h0.y = __float2half_rn(x.y);
    __half2 h1; h1.x = __float2half_rn(x.z); h1.y = __float2half_rn(x.w);
    ((__half2*)hi)[2 * i + 0] = h0;
    ((__half2*)hi)[2 * i + 1] = h1;
}

// ---------------- mma.sync fp16 GEMM (NT), R12 config (frozen) --------------
#define GM  128
#define GN  128
#define GKC 32
#define NCHUNK (Kdim / GKC)       // 16
#define APITCH 80
#define MAT_BYTES (128 * APITCH)  // 10240
#define STAGE_BYTES (2 * MAT_BYTES)   // 20480
#define GEMM_SMEM (3 * STAGE_BYTES)   // 61440

__global__ void __launch_bounds__(256, 2)
gemm_tc(const __half* __restrict__ Ahi, const __half* __restrict__ Bhi,
        const float* __restrict__ bias, float* __restrict__ Cf,
        __half* __restrict__ Ch, int Nc, int out_half)
{
    extern __shared__ char smem[];
    const uint32_t sb = smem_u32(smem);
    const int t = threadIdx.x, wid = t >> 5, lane = t & 31;
    const int bm = blockIdx.y * GM, bn = blockIdx.x * GN;
    const int wm = (wid & 3) * 32;
    const int wn = (wid >> 2) * 64;

    float acc[2][8][4];
#pragma unroll
    for (int i = 0; i < 2; ++i)
#pragma unroll
        for (int j = 0; j < 8; ++j)
#pragma unroll
            for (int q = 0; q < 4; ++q) acc[i][j][q] = 0.0f;

    auto load_stage = [&](int st, int k0) {
        uint32_t base = sb + st * (uint32_t)STAGE_BYTES;
#pragma unroll
        for (int it = 0; it < 2; ++it) {
            int idx = t + 256 * it;
            int r = idx >> 2, seg = idx & 3;
            uint32_t doff = (uint32_t)(r * APITCH + seg * 16);
            size_t soA = (size_t)(bm + r) * Kdim + k0 + seg * 8;
            size_t soB = (size_t)(bn + r) * Kdim + k0 + seg * 8;
            cp16(base + doff,             Ahi + soA);
            cp16(base + MAT_BYTES + doff, Bhi + soB);
        }
        CP_COMMIT();
    };

    load_stage(0, 0);
    load_stage(1, GKC);

    const uint32_t lrow  = lane & 15;
    const uint32_t lcolb = (lane >> 4) * 16;

    for (int c = 0; c < NCHUNK; ++c) {
        if (c + 2 < NCHUNK) {
            load_stage((c + 2) % 3, (c + 2) * GKC);
            CP_WAIT2();
        } else if (c + 1 < NCHUNK) {
            CP_WAIT1();
        } else {
            CP_WAIT0();
        }
        __syncthreads();

        uint32_t base = sb + (uint32_t)(c % 3) * STAGE_BYTES;
#pragma unroll
        for (int s = 0; s < 2; ++s) {
            uint32_t colb = s * 32 + lcolb;
            uint32_t Ah[2][4];
#pragma unroll
            for (int mi = 0; mi < 2; ++mi) {
                uint32_t ad = base + (wm + mi * 16 + lrow) * APITCH + colb;
                LDSM4(Ah[mi][0], Ah[mi][1], Ah[mi][2], Ah[mi][3], ad);
            }
#pragma unroll
            for (int ni = 0; ni < 4; ++ni) {
                uint32_t bd = base + MAT_BYTES
                            + (wn + ni * 16 + lrow) * APITCH + colb;
                uint32_t h0, h1, h2, h3;
                LDSM4(h0, h1, h2, h3, bd);
#pragma unroll
                for (int mi = 0; mi < 2; ++mi) {
                    MMA16816(acc[mi][2 * ni],     Ah[mi], h0, h2);
                    MMA16816(acc[mi][2 * ni + 1], Ah[mi], h1, h3);
                }
            }
        }
        __syncthreads();
    }

    const int row0 = bm + wm + (lane >> 2);
    const int col0 = bn + wn + (lane & 3) * 2;
    if (out_half) {
#pragma unroll
        for (int mi = 0; mi < 2; ++mi) {
#pragma unroll
            for (int nj = 0; nj < 8; ++nj) {
                int r = row0 + mi * 16;
                int cc = col0 + nj * 8;
                float b0 = __ldg(&bias[cc]), b1 = __ldg(&bias[cc + 1]);
                __half2 v0, v1;
                v0.x = __float2half_rn(acc[mi][nj][0] + b0);
                v0.y = __float2half_rn(acc[mi][nj][1] + b1);
                v1.x = __float2half_rn(acc[mi][nj][2] + b0);
                v1.y = __float2half_rn(acc[mi][nj][3] + b1);
                *(__half2*)&Ch[(size_t)r * Nc + cc]       = v0;
                *(__half2*)&Ch[(size_t)(r + 8) * Nc + cc] = v1;
            }
        }
    } else {
#pragma unroll
        for (int mi = 0; mi < 2; ++mi) {
#pragma unroll
            for (int nj = 0; nj < 8; ++nj) {
                int r = row0 + mi * 16;
                int cc = col0 + nj * 8;
                float b0 = __ldg(&bias[cc]), b1 = __ldg(&bias[cc + 1]);
                float* p0 = Cf + (size_t)r * Nc + cc;
                float* p1 = Cf + (size_t)(r + 8) * Nc + cc;
                p0[0] = acc[mi][nj][0] + b0;
                p0[1] = acc[mi][nj][1] + b1;
                p1[0] = acc[mi][nj][2] + b0;
                p1[1] = acc[mi][nj][3] + b1;
            }
        }
    }
}

// ============================================================================
// Tensor-core attention: one warp per (b,h). 4 warps/block, no block syncs.
// Scores = NT mma (Q,K fp16 k-major) -> fp32 acc; softmax on fragments
// (exact expf, attn written fp32 BEFORE any P rounding); P packed to fp16
// A-fragments (acc layout == A layout); PV B via ldmatrix.trans on V rows.
// ctx staged via smem for coalesced fp16 stores.
// ============================================================================
#define AW_Q 0
#define AW_K 4608
#define AW_V 9216
#define AW_BYTES 13824
#define ATTN_SMEM (4 * AW_BYTES)   // 55296

__global__ void __launch_bounds__(128, 3)
attn_mma(const __half* __restrict__ qkv, __half* __restrict__ chi,
         float* __restrict__ attn_out)
{
    extern __shared__ char asmem[];
    const int t = threadIdx.x, wid = t >> 5, lane = t & 31;
    const int bh = blockIdx.x * 4 + wid;
    const int b = bh >> 3, h = bh & 7;
    char* sp = asmem + wid * AW_BYTES;
    const uint32_t ws = smem_u32(asmem) + wid * AW_BYTES;

    // ---- load Q,K,V (32 rows x 64 halves, pitch 144B) ----
    const __half* base = qkv + (size_t)b * (Nn * QKV_COLS) + h * Dd;
#pragma unroll
    for (int it = 0; it < 8; ++it) {
        int task = it * 32 + lane;
        int r = task >> 3, seg = task & 7;
        size_t ro = (size_t)r * QKV_COLS + seg * 8;
        uint4 qv = *(const uint4*)&base[ro];
        uint4 kv = *(const uint4*)&base[ro + HIDd];
        uint4 vv = *(const uint4*)&base[ro + 2 * HIDd];
        uint32_t doff = (uint32_t)(r * 144 + seg * 16);
        *(uint4*)(sp + AW_Q + doff) = qv;
        *(uint4*)(sp + AW_K + doff) = kv;
        *(uint4*)(sp + AW_V + doff) = vv;
    }
    __syncwarp();

    // ---- scores: c[mi][ni][q], m=32, n=32, k=64 ----
    float c[2][4][4];
#pragma unroll
    for (int i = 0; i < 2; ++i)
#pragma unroll
        for (int j = 0; j < 4; ++j)
#pragma unroll
            for (int q = 0; q < 4; ++q) c[i][j][q] = 0.0f;

    const uint32_t lrow = lane & 15;
    const uint32_t lhi  = (lane >> 4) * 16;
#pragma unroll
    for (int kt = 0; kt < 4; ++kt) {
        uint32_t colb = kt * 32 + lhi;
        uint32_t QA[2][4];
#pragma unroll
        for (int mi = 0; mi < 2; ++mi) {
            uint32_t ad = ws + AW_Q + (mi * 16 + lrow) * 144 + colb;
            LDSM4(QA[mi][0], QA[mi][1], QA[mi][2], QA[mi][3], ad);
        }
#pragma unroll
        for (int ng = 0; ng < 2; ++ng) {
            uint32_t bd = ws + AW_K + (ng * 16 + lrow) * 144 + colb;
            uint32_t h0, h1, h2, h3;
            LDSM4(h0, h1, h2, h3, bd);
#pragma unroll
            for (int mi = 0; mi < 2; ++mi) {
                MMA16816(c[mi][2 * ng],     QA[mi], h0, h2);
                MMA16816(c[mi][2 * ng + 1], QA[mi], h1, h3);
            }
        }
    }

    // ---- mask + softmax (per row over 4-lane quad), write attn fp32 ----
    size_t abase = (size_t)bh * 1024;
#pragma unroll
    for (int mi = 0; mi < 2; ++mi) {
#pragma unroll
        for (int qh = 0; qh < 2; ++qh) {
            int i = mi * 16 + qh * 8 + (lane >> 2);
            unsigned bits = g_mask_bits[i];
            float v[8];
#pragma unroll
            for (int ni = 0; ni < 4; ++ni) {
                int j0 = ni * 8 + (lane & 3) * 2;
                float s0 = c[mi][ni][qh * 2 + 0];
                float s1 = c[mi][ni][qh * 2 + 1];
                v[2 * ni]     = ((bits >> j0) & 1u)       ? s0 * 0.125f : -1e9f;
                v[2 * ni + 1] = ((bits >> (j0 + 1)) & 1u) ? s1 * 0.125f : -1e9f;
            }
            float mx = v[0];
#pragma unroll
            for (int k = 1; k < 8; ++k) mx = fmaxf(mx, v[k]);
            mx = fmaxf(mx, __shfl_xor_sync(0xFFFFFFFFu, mx, 1));
            mx = fmaxf(mx, __shfl_xor_sync(0xFFFFFFFFu, mx, 2));
            float sum = 0.0f;
#pragma unroll
            for (int k = 0; k < 8; ++k) { v[k] = expf(v[k] - mx); sum += v[k]; }
            sum += __shfl_xor_sync(0xFFFFFFFFu, sum, 1);
            sum += __shfl_xor_sync(0xFFFFFFFFu, sum, 2);
            float inv = 1.0f / sum;
#pragma unroll
            for (int ni = 0; ni < 4; ++ni) {
                float p0 = v[2 * ni] * inv, p1 = v[2 * ni + 1] * inv;
                c[mi][ni][qh * 2 + 0] = p0;
                c[mi][ni][qh * 2 + 1] = p1;
                *(float2*)&attn_out[abase + (size_t)i * 32 + ni * 8 + (lane & 3) * 2]
                    = make_float2(p0, p1);
            }
        }
    }

    // ---- pack P -> fp16 A fragments (acc layout == A layout) ----
    uint32_t RP[2][2][4];
#pragma unroll
    for (int mi = 0; mi < 2; ++mi)
#pragma unroll
        for (int kt = 0; kt < 2; ++kt) {
            RP[mi][kt][0] = pkh2(c[mi][kt * 2][0],     c[mi][kt * 2][1]);
            RP[mi][kt][1] = pkh2(c[mi][kt * 2][2],     c[mi][kt * 2][3]);
            RP[mi][kt][2] = pkh2(c[mi][kt * 2 + 1][0], c[mi][kt * 2 + 1][1]);
            RP[mi][kt][3] = pkh2(c[mi][kt * 2 + 1][2], c[mi][kt * 2 + 1][3]);
        }

    // ---- PV: m=32, n=64(d), k=32(j); B via trans-LDSM on V rows ----
    float acc2[2][8][4];
#pragma unroll
    for (int i = 0; i < 2; ++i)
#pragma unroll
        for (int j = 0; j < 8; ++j)
#pragma unroll
            for (int q = 0; q < 4; ++q) acc2[i][j][q] = 0.0f;

    const int m4 = lane >> 3;   // matrix id 0..3
#pragma unroll
    for (int kt = 0; kt < 2; ++kt) {
#pragma unroll
        for (int g = 0; g < 4; ++g) {
            uint32_t ad = ws + AW_V
                        + (kt * 16 + (m4 & 1) * 8 + (lane & 7)) * 144
                        + g * 32 + (m4 >> 1) * 16;
            uint32_t r0, r1, r2, r3;
            LDSM4T(r0, r1, r2, r3, ad);
#pragma unroll
            for (int mi = 0; mi < 2; ++mi) {
                MMA16816(acc2[mi][2 * g],     RP[mi][kt], r0, r1);
                MMA16816(acc2[mi][2 * g + 1], RP[mi][kt], r2, r3);
            }
        }
    }
    __syncwarp();

    // ---- stage ctx fp16 into K region (pitch 144B), then coalesced out ----
#pragma unroll
    for (int mi = 0; mi < 2; ++mi)
#pragma unroll
        for (int qh = 0; qh < 2; ++qh) {
            int i = mi * 16 + qh * 8 + (lane >> 2);
#pragma unroll
            for (int nd = 0; nd < 8; ++nd) {
                int d = nd * 8 + (lane & 3) * 2;
                __half2 hv = __floats2half2_rn(acc2[mi][nd][qh * 2],
                                               acc2[mi][nd][qh * 2 + 1]);
                *(__half2*)(sp + AW_K + i * 144 + d * 2) = hv;
            }
        }
    __syncwarp();

    __half* crow = chi + (size_t)b * (Nn * HIDd) + h * Dd;
#pragma unroll
    for (int it = 0; it < 8; ++it) {
        int task = it * 32 + lane;
        int r = task >> 3, seg = task & 7;
        uint4 vv = *(uint4*)(sp + AW_K + r * 144 + seg * 16);
        *(uint4*)&crow[(size_t)r * HIDd + seg * 8] = vv;
    }
}

// ---------------- launch ----------------
extern "C" void kernel_launch(void* const* d_in, const int* in_sizes, int n_in,
                              void* d_out, int out_size) {
    const float*         X    = (const float*)d_in[0];
    const unsigned char* mask = (const unsigned char*)d_in[1];
    const float*         Wqkv = (const float*)d_in[2];
    const float*         bqkv = (const float*)d_in[3];
    const float*         Wo   = (const float*)d_in[4];
    const float*         bo   = (const float*)d_in[5];

    float *outfb_p, *attn_fb_p;
    __half *qkvh_p, *ahi_p, *whi_p;
    cudaGetSymbolAddress((void**)&outfb_p, g_outfb);
    cudaGetSymbolAddress((void**)&attn_fb_p, g_attn_fb);
    cudaGetSymbolAddress((void**)&qkvh_p, g_qkvh);
    cudaGetSymbolAddress((void**)&ahi_p, g_Ahi);
    cudaGetSymbolAddress((void**)&whi_p, g_Whi);

    float* out = (float*)d_out;
    float *out_p, *attn_p;
    long long osz = (long long)out_size;
    if (osz >= (long long)(OUT_ELEMS + ATTN_ELEMS)) {
        out_p = out; attn_p = out + OUT_ELEMS;
    } else if (osz >= (long long)OUT_ELEMS) {
        out_p = out; attn_p = attn_fb_p;
    } else {
        attn_p = out; out_p = outfb_p;
    }

    cudaFuncSetAttribute(gemm_tc, cudaFuncAttributeMaxDynamicSharedMemorySize,
                         GEMM_SMEM);
    cudaFuncSetAttribute(attn_mma, cudaFuncAttributeMaxDynamicSharedMemorySize,
                         ATTN_SMEM);

    decode_mask_kernel<<<1, 32>>>(mask);

    // converts: X, Wqkv, Wo -> fp16
    {
        int n4 = (MROWS * HIDd) / 4;
        split_hi_kernel<<<(n4 + 255) / 256, 256>>>(X, ahi_p, n4);
        int w4 = WQKV_ELE / 4;
        split_hi_kernel<<<(w4 + 255) / 256, 256>>>(Wqkv, whi_p, w4);
        int o4 = (HIDd * HIDd) / 4;
        split_hi_kernel<<<(o4 + 255) / 256, 256>>>(Wo, whi_p + WQKV_ELE, o4);
    }

    // qkv = X @ Wqkv^T + bqkv   [131072 x 1536], fp16 output
    gemm_tc<<<dim3(QKV_COLS / GN, MROWS / GM), 256, GEMM_SMEM>>>(
        ahi_p, whi_p, bqkv, nullptr, qkvh_p, QKV_COLS, 1);

    // attention: tensor-core warp-per-(b,h); attn fp32 + ctx fp16 into g_Ahi
    attn_mma<<<(Bsz * Hh) / 4, 128, ATTN_SMEM>>>(qkvh_p, ahi_p, attn_p);

    // out = ctx @ Wo^T + bo     [131072 x 512], fp32 output
    gemm_tc<<<dim3(HIDd / GN, MROWS / GM), 256, GEMM_SMEM>>>(
        ahi_p, whi_p + WQKV_ELE, bo, out_p, nullptr, HIDd, 0);
}